// round 13
// baseline (speedup 1.0000x reference)
#include <cuda_runtime.h>
#include <cuda_bf16.h>
#include <math.h>
#include <stdint.h>

#define BATCH 128
#define NPTS  1024
#define DIM   128
#define UMAX  0xFFFFFFFFu

// g_D holds PACKED keys: high 22 bits = RTN of dist^2 float bits, low 10 bits
// = column index. Monotone in dist^2; ties -> lower index (matches jnp.argmin).
__device__ uint32_t       g_D[(size_t)BATCH * NPTS * NPTS];   // 512 MB
__device__ __nv_bfloat16  g_Xb[(size_t)BATCH * NPTS * DIM];   // 32 MB
__device__ float          g_norm[BATCH * NPTS];
__device__ float          g_partial[BATCH];
__device__ uint32_t       g_nn8[(size_t)BATCH * NPTS * 8];    // top-8 NN keys/point (4 MB)

// ---------------------------------------------------------------------------
// Kernel 1: fused row norms (fp32 exact) + bf16 conversion. One warp per point.
// ---------------------------------------------------------------------------
__global__ void prep_kernel(const float* __restrict__ X) {
    int warp = (blockIdx.x * blockDim.x + threadIdx.x) >> 5;
    int lane = threadIdx.x & 31;
    if (warp >= BATCH * NPTS) return;
    const float4* row = (const float4*)(X + (size_t)warp * DIM);
    float4 v = row[lane];
    __nv_bfloat162* dst = (__nv_bfloat162*)(g_Xb + (size_t)warp * DIM) + lane * 2;
    dst[0] = __floats2bfloat162_rn(v.x, v.y);
    dst[1] = __floats2bfloat162_rn(v.z, v.w);
    float s = v.x * v.x + v.y * v.y + v.z * v.z + v.w * v.w;
    #pragma unroll
    for (int o = 16; o; o >>= 1) s += __shfl_down_sync(0xffffffffu, s, o);
    if (lane == 0) g_norm[warp] = s;
}

// ---------------------------------------------------------------------------
// Kernel 2: batched Gram via bf16 mma.sync; epilogue packs dist^2 keys.
// ---------------------------------------------------------------------------
#define KCH   64
#define LDR   72

__device__ __forceinline__ void mma16816(float* c, const uint32_t* a,
                                         uint32_t b0, uint32_t b1) {
    asm volatile(
        "mma.sync.aligned.m16n8k16.row.col.f32.bf16.bf16.f32 "
        "{%0,%1,%2,%3}, {%4,%5,%6,%7}, {%8,%9}, {%0,%1,%2,%3};\n"
        : "+f"(c[0]), "+f"(c[1]), "+f"(c[2]), "+f"(c[3])
        : "r"(a[0]), "r"(a[1]), "r"(a[2]), "r"(a[3]), "r"(b0), "r"(b1));
}

__device__ __forceinline__ uint32_t pack_key(float d2, int col) {
    return ((__float_as_uint(d2) + 0x200u) & 0xFFFFFC00u) | (uint32_t)col;
}

__global__ __launch_bounds__(256, 2)
void dist_kernel() {
    __shared__ __align__(16) __nv_bfloat16 As[128 * LDR];
    __shared__ __align__(16) __nv_bfloat16 Bs[128 * LDR];

    const int b  = blockIdx.z;
    const int I  = blockIdx.y * 128;
    const int J  = blockIdx.x * 128;
    const int tid  = threadIdx.x;
    const int lane = tid & 31;
    const int wid  = tid >> 5;
    const int wm   = wid & 3;
    const int wn   = wid >> 2;

    const __nv_bfloat16* Xb = g_Xb + (size_t)b * NPTS * DIM;

    float acc[2][8][4];
    #pragma unroll
    for (int m = 0; m < 2; ++m)
        #pragma unroll
        for (int n = 0; n < 8; ++n)
            #pragma unroll
            for (int q = 0; q < 4; ++q) acc[m][n][q] = 0.f;

    const uint32_t* As32 = (const uint32_t*)As;
    const uint32_t* Bs32 = (const uint32_t*)Bs;

    for (int k0 = 0; k0 < DIM; k0 += KCH) {
        __syncthreads();
        #pragma unroll
        for (int i = 0; i < 4; ++i) {
            int e  = tid + 256 * i;
            int r  = e >> 3;
            int c8 = e & 7;
            uint4 va = *(const uint4*)(Xb + (size_t)(I + r) * DIM + k0 + c8 * 8);
            uint4 vb = *(const uint4*)(Xb + (size_t)(J + r) * DIM + k0 + c8 * 8);
            *(uint4*)(As + r * LDR + c8 * 8) = va;
            *(uint4*)(Bs + r * LDR + c8 * 8) = vb;
        }
        __syncthreads();

        #pragma unroll
        for (int ks = 0; ks < KCH / 16; ++ks) {
            const int c = ks * 16 + (lane & 3) * 2;
            uint32_t a[2][4];
            #pragma unroll
            for (int mt = 0; mt < 2; ++mt) {
                int r0 = wm * 32 + mt * 16 + (lane >> 2);
                a[mt][0] = As32[(r0 * LDR + c) >> 1];
                a[mt][1] = As32[((r0 + 8) * LDR + c) >> 1];
                a[mt][2] = As32[(r0 * LDR + c + 8) >> 1];
                a[mt][3] = As32[((r0 + 8) * LDR + c + 8) >> 1];
            }
            #pragma unroll
            for (int nt = 0; nt < 8; ++nt) {
                int jr = wn * 64 + nt * 8 + (lane >> 2);
                uint32_t b0 = Bs32[(jr * LDR + c) >> 1];
                uint32_t b1 = Bs32[(jr * LDR + c + 8) >> 1];
                mma16816(acc[0][nt], a[0], b0, b1);
                mma16816(acc[1][nt], a[1], b0, b1);
            }
        }
    }

    uint32_t* Db = g_D + ((size_t)b << 20);
    const float* nb = g_norm + b * NPTS;
    #pragma unroll
    for (int mt = 0; mt < 2; ++mt) {
        int r0 = I + wm * 32 + mt * 16 + (lane >> 2);
        float ni0 = nb[r0], ni1 = nb[r0 + 8];
        #pragma unroll
        for (int nt = 0; nt < 8; ++nt) {
            int col = J + wn * 64 + nt * 8 + (lane & 3) * 2;
            float nj0 = nb[col], nj1 = nb[col + 1];
            uint2 v0, v1;
            v0.x = pack_key(fmaxf(ni0 + nj0 - 2.f * acc[mt][nt][0], 0.f), col);
            v0.y = pack_key(fmaxf(ni0 + nj1 - 2.f * acc[mt][nt][1], 0.f), col + 1);
            v1.x = pack_key(fmaxf(ni1 + nj0 - 2.f * acc[mt][nt][2], 0.f), col);
            v1.y = pack_key(fmaxf(ni1 + nj1 - 2.f * acc[mt][nt][3], 0.f), col + 1);
            *(uint2*)(Db + (size_t)r0 * NPTS + col)           = v0;
            *(uint2*)(Db + (size_t)(r0 + 8) * NPTS + col)     = v1;
        }
    }
}

// ---------------------------------------------------------------------------
// Kernel 2b: exact top-8 NN keys per point. One warp per row of g_D.
// Per-lane sorted top-8 over 32 values (bubble insert), then 8 REDUX
// extraction rounds. Diagonal (key idx == row) excluded.
// ---------------------------------------------------------------------------
__global__ __launch_bounds__(256)
void nn8_kernel() {
    const int gw   = (blockIdx.x * 256 + threadIdx.x) >> 5;  // row id
    const int lane = threadIdx.x & 31;
    const uint32_t rowid = (uint32_t)(gw & 1023);
    const uint4* R = (const uint4*)(g_D + ((size_t)gw << 10));

    uint32_t t0=UMAX,t1=UMAX,t2=UMAX,t3=UMAX,t4=UMAX,t5=UMAX,t6=UMAX,t7=UMAX;

    #define NN_INS(kk) do { uint32_t x=(kk); \
        if (x < t7 && (x & 1023u) != rowid) { \
            t7 = x; uint32_t lo, hi; \
            lo=min(t6,t7); hi=max(t6,t7); t6=lo; t7=hi; \
            lo=min(t5,t6); hi=max(t5,t6); t5=lo; t6=hi; \
            lo=min(t4,t5); hi=max(t4,t5); t4=lo; t5=hi; \
            lo=min(t3,t4); hi=max(t3,t4); t3=lo; t4=hi; \
            lo=min(t2,t3); hi=max(t2,t3); t2=lo; t3=hi; \
            lo=min(t1,t2); hi=max(t1,t2); t1=lo; t2=hi; \
            lo=min(t0,t1); hi=max(t0,t1); t0=lo; t1=hi; \
        } } while(0)

    #pragma unroll
    for (int q = 0; q < 8; ++q) {
        uint4 v = R[lane + 32 * q];
        NN_INS(v.x); NN_INS(v.y); NN_INS(v.z); NN_INS(v.w);
    }

    // 8 extraction rounds: warp-min of heads; unique keys -> one winner pops.
    #define NN_EXTRACT(wv) do { \
        uint32_t g = __reduce_min_sync(0xffffffffu, t0); \
        if (t0 == g) { t0=t1; t1=t2; t2=t3; t3=t4; t4=t5; t5=t6; t6=t7; t7=UMAX; } \
        wv = g; } while(0)

    uint32_t w0,w1,w2,w3,w4,w5,w6,w7;
    NN_EXTRACT(w0); NN_EXTRACT(w1); NN_EXTRACT(w2); NN_EXTRACT(w3);
    NN_EXTRACT(w4); NN_EXTRACT(w5); NN_EXTRACT(w6); NN_EXTRACT(w7);

    if (lane == 0) {
        uint4* out = (uint4*)(g_nn8 + ((size_t)gw << 3));
        out[0] = make_uint4(w0, w1, w2, w3);
        out[1] = make_uint4(w4, w5, w6, w7);
    }
}

// ---------------------------------------------------------------------------
// Kernel 3: Prim's MST with lazy row commit + exact NN-table term2.
// Selection at iter t: next = min( term1, term2 ) where
//   term1 = min over e of (e==pend ? UMAX : m_e)          [m committed thru
//           the vertex BEFORE pend; visited entries are UMAX]
//   term2 = min over unvisited e of d(pend, e)
//         = first unvisited entry of pend's sorted top-8 NN keys (exact,
//           since keys beyond top-8 are all >= them); if all 8 visited ->
//           exact fallback: one extra reduction round over the pending row
//           (which by then has ~a full iteration of fetch lead).
// Pending row commit happens in phase B (after selection) -> its LDG, issued
// last iteration, gets ~T cycles of lead: T = F + max(0, L - T).
// Identical selection math -> identical MST -> rel_err must not change.
// ---------------------------------------------------------------------------
__global__ __launch_bounds__(256, 1)
void prim_kernel() {
    const int b    = blockIdx.x;
    const int tid  = threadIdx.x;
    const int lane = tid & 31;
    const int wid  = tid >> 5;
    const int p0   = tid * 4;

    const uint32_t* Db = g_D + ((size_t)b << 20);

    __shared__ __align__(16) uint32_t s_nn[NPTS * 8];   // 32 KB sorted NN keys
    __shared__ uint32_t s_vis[32];                      // visited bitmask
    __shared__ uint32_t s_w1[2][8];                     // round-1 warp mins
    __shared__ uint32_t s_w2[2][8];                     // fallback round mins

    // prologue: stage NN table, init bitmask / mind / pending row 0
    #pragma unroll
    for (int q = 0; q < 8; ++q)
        ((uint4*)s_nn)[tid + 256 * q] = ((const uint4*)g_nn8)[((size_t)b << 11) + tid + 256 * q];
    if (tid < 32) s_vis[tid] = (tid == 0) ? 1u : 0u;    // vertex 0 visited

    uint4 m = ((const uint4*)Db)[tid];                  // row 0 keys
    if (tid == 0) m.x = UMAX;
    int  pend = 0;
    uint4 PR  = ((const uint4*)Db)[tid];                // pending row = row 0
    __syncthreads();

    float total = 0.f;

    for (int it = 0; it < NPTS - 1; ++it) {
        const int par = it & 1;

        // ---- term1: reduce m with pend excluded ----
        uint32_t c0 = (p0 + 0 == pend) ? UMAX : m.x;
        uint32_t c1 = (p0 + 1 == pend) ? UMAX : m.y;
        uint32_t c2 = (p0 + 2 == pend) ? UMAX : m.z;
        uint32_t c3 = (p0 + 3 == pend) ? UMAX : m.w;
        uint32_t km = min(min(c0, c1), min(c2, c3));
        uint32_t wbest = __reduce_min_sync(0xffffffffu, km);
        if (lane == 0) s_w1[par][wid] = wbest;
        __syncthreads();
        uint4 a0 = *(const uint4*)&s_w1[par][0];
        uint4 a1 = *(const uint4*)&s_w1[par][4];
        uint32_t term1 = min(min(min(a0.x, a0.y), min(a0.z, a0.w)),
                             min(min(a1.x, a1.y), min(a1.z, a1.w)));

        // ---- term2: first unvisited static NN of pend (block-uniform) ----
        const uint32_t* nn = s_nn + (pend << 3);
        uint4 na = *(const uint4*)nn;
        uint4 nb4 = *(const uint4*)(nn + 4);
        uint32_t term2 = UMAX;
        #define NN_CHK(kk) if (term2 == UMAX) { uint32_t ii = (kk) & 1023u; \
            if (!((s_vis[ii >> 5] >> (ii & 31)) & 1u)) term2 = (kk); }
        NN_CHK(na.x) NN_CHK(na.y) NN_CHK(na.z) NN_CHK(na.w)
        NN_CHK(nb4.x) NN_CHK(nb4.y) NN_CHK(nb4.z) NN_CHK(nb4.w)
        #undef NN_CHK

        if (term2 == UMAX) {
            // fallback (uniform): exact min over unvisited of pending row PR
            uint32_t f0 = (m.x == UMAX || p0 + 0 == pend) ? UMAX : PR.x;
            uint32_t f1 = (m.y == UMAX || p0 + 1 == pend) ? UMAX : PR.y;
            uint32_t f2 = (m.z == UMAX || p0 + 2 == pend) ? UMAX : PR.z;
            uint32_t f3 = (m.w == UMAX || p0 + 3 == pend) ? UMAX : PR.w;
            uint32_t fk = min(min(f0, f1), min(f2, f3));
            uint32_t wf = __reduce_min_sync(0xffffffffu, fk);
            if (lane == 0) s_w2[par][wid] = wf;
            __syncthreads();
            uint4 b0 = *(const uint4*)&s_w2[par][0];
            uint4 b1 = *(const uint4*)&s_w2[par][4];
            term2 = min(min(min(b0.x, b0.y), min(b0.z, b0.w)),
                        min(min(b1.x, b1.y), min(b1.z, b1.w)));
        }

        uint32_t best = min(term1, term2);
        int jnew = (int)(best & 1023u);
        if (tid == 0) total += sqrtf(__uint_as_float(best & 0xFFFFFC00u));

        // ---- issue next pending row load ASAP (full-iteration lead) ----
        uint4 PRnew = ((const uint4*)(Db + ((size_t)jnew << 10)))[tid];

        // ---- phase B: commit pending row into m (sticky, pend -> UMAX) ----
        m.x = (m.x == UMAX || p0 + 0 == pend) ? UMAX : min(m.x, PR.x);
        m.y = (m.y == UMAX || p0 + 1 == pend) ? UMAX : min(m.y, PR.y);
        m.z = (m.z == UMAX || p0 + 2 == pend) ? UMAX : min(m.z, PR.z);
        m.w = (m.w == UMAX || p0 + 3 == pend) ? UMAX : min(m.w, PR.w);

        if (tid == 0) s_vis[jnew >> 5] |= (1u << (jnew & 31));  // visible after next BAR
        pend = jnew;
        PR   = PRnew;
    }
    if (tid == 0) g_partial[b] = total;
}

// ---------------------------------------------------------------------------
// Kernel 4: final scalar.
// ---------------------------------------------------------------------------
__global__ void final_kernel(float* __restrict__ out) {
    const int t = threadIdx.x;           // 128 threads
    const int lane = t & 31, wid = t >> 5;
    __shared__ float s[4];
    float v = g_partial[t];
    #pragma unroll
    for (int o = 16; o; o >>= 1) v += __shfl_down_sync(0xffffffffu, v, o);
    if (lane == 0) s[wid] = v;
    __syncthreads();
    if (t == 0) out[0] = (s[0] + s[1] + s[2] + s[3]) / (1023.f * (float)BATCH * 2.f);
}

// ---------------------------------------------------------------------------
extern "C" void kernel_launch(void* const* d_in, const int* in_sizes, int n_in,
                              void* d_out, int out_size) {
    (void)in_sizes; (void)n_in; (void)out_size;
    const float* X = (const float*)d_in[0];
    float* out = (float*)d_out;

    prep_kernel<<<16384, 256>>>(X);            // fused norms + bf16 convert
    dist_kernel<<<dim3(8, 8, BATCH), 256>>>();
    nn8_kernel<<<BATCH * NPTS / 8, 256>>>();   // exact top-8 NN keys per point
    prim_kernel<<<BATCH, 256>>>();
    final_kernel<<<1, 128>>>(out);
}